// round 14
// baseline (speedup 1.0000x reference)
#include <cuda_runtime.h>
#include <math.h>

#define NB 16
#define NT 256
#define NC 64
#define NF 128
#define NGO 32
#define NH 32
#define XP 34    // u64 row stride for 32-slot paired smem arrays
#define GGRID 456  // kGW grid: 3 blocks/SM x 152 SMs, single wave

typedef unsigned long long u64;

// ---------------- packed f32x2 helpers ----------------
__device__ __forceinline__ u64 PK(float x, float y) {
    u64 r;
    asm("mov.b64 %0, {%1,%2};" : "=l"(r) : "f"(x), "f"(y));
    return r;
}
__device__ __forceinline__ float2 UPK(u64 v) {
    float2 f;
    asm("mov.b64 {%0,%1}, %2;" : "=f"(f.x), "=f"(f.y) : "l"(v));
    return f;
}
__device__ __forceinline__ u64 FFMA2(u64 a, u64 b, u64 c) {
    u64 d;
    asm("fma.rn.f32x2 %0, %1, %2, %3;" : "=l"(d) : "l"(a), "l"(b), "l"(c));
    return d;
}
__device__ __forceinline__ float HSUM(u64 v) {
    float2 f = UPK(v);
    return f.x + f.y;
}
__device__ __forceinline__ float fast_tanh(float x) {
    float e = __expf(2.0f * x);
    return 1.0f - __fdividef(2.0f, e + 1.0f);
}
__device__ __forceinline__ float fast_sig(float x) {
    return 1.0f / (1.0f + __expf(-x));
}

// ---------------- scratch ----------------
__device__ float g_sm[NC * NF];
__device__ float g_A[NB * NC * NC];
__device__ u64 g_abits[NB * NC];             // adjacency bitmask per row
__device__ float g_Wh[NB * NT * NC * NGO];   // [bt][c][j]
__device__ float g_hp[NB * NT * NH];
__device__ float g_gx[2 * NB * NT * 4 * NH];
__device__ float g_hl[NB * NT * 2 * NH];
__device__ float g_sc[NB * NT];

// ---------------- kernel 0: zero A + row softmax of spectral_w ----------------
__global__ void k_sm(const float* __restrict__ sw) {
    int c = blockIdx.x, f = threadIdx.x;
    {
        int base = blockIdx.x * 1024;
#pragma unroll
        for (int i = threadIdx.x; i < 1024; i += 128) g_A[base + i] = 0.0f;
    }
    float v = sw[c * NF + f];
    __shared__ float rm[4], rs[4];
    int lane = f & 31, w = f >> 5;
    float m = v;
#pragma unroll
    for (int o = 16; o; o >>= 1) m = fmaxf(m, __shfl_xor_sync(0xffffffffu, m, o));
    if (lane == 0) rm[w] = m;
    __syncthreads();
    m = fmaxf(fmaxf(rm[0], rm[1]), fmaxf(rm[2], rm[3]));
    float e = __expf(v - m);
    float s = e;
#pragma unroll
    for (int o = 16; o; o >>= 1) s += __shfl_xor_sync(0xffffffffu, s, o);
    if (lane == 0) rs[w] = s;
    __syncthreads();
    s = rs[0] + rs[1] + rs[2] + rs[3];
    g_sm[c * NF + f] = e / s;
}

// ---------------- kernel GW: Gram + Wh fused, balanced persistent chunks ----------------
extern __shared__ u64 shG[];
__global__ void __launch_bounds__(256, 3) kGW(const float* __restrict__ x,
                                              const float* __restrict__ gatW) {
    u64* xA  = shG;                      // [64][XP]
    u64* xB  = shG + 64 * XP;            // [64][XP]
    u64* swP = shG + 2 * 64 * XP;        // [64 f2][XP slots j]
    float* invn = (float*)(shG + 3 * 64 * XP);           // [64]
    float* accS = (float*)(shG + 3 * 64 * XP + 32);      // [16][256] per-thread acc

    const int tid = threadIdx.x;
    const int ty = tid >> 4, tx = tid & 15;

    const int bid = blockIdx.x;
    const int sIt = (bid * (NB * NT)) / GGRID;
    const int eIt = ((bid + 1) * (NB * NT)) / GGRID;

    for (int i = tid; i < 64 * NGO; i += 256) {
        int f2 = i >> 5, j = i & 31;
        swP[f2 * XP + j] = PK(gatW[(2 * f2) * NGO + j], gatW[(2 * f2 + 1) * NGO + j]);
    }
#pragma unroll
    for (int i = 0; i < 16; i++) accS[i * 256 + tid] = 0.0f;

    int cur_b = sIt >> 8;
    for (int bt = sIt; bt < eIt; bt++) {
        const int b = bt >> 8;
        if (b != cur_b) {
            float* Ab = g_A + cur_b * NC * NC;
#pragma unroll
            for (int r = 0; r < 4; r++)
#pragma unroll
                for (int c = 0; c < 4; c++) {
                    atomicAdd(&Ab[(ty * 4 + r) * NC + tx * 4 + c],
                              accS[(r * 4 + c) * 256 + tid]);
                    accS[(r * 4 + c) * 256 + tid] = 0.0f;
                }
            cur_b = b;
        }
        {
            const float2* x2 = (const float2*)(x + (size_t)bt * NC * NF);
            const float2* s2 = (const float2*)g_sm;
            for (int i = tid; i < NC * NF / 2; i += 256) {
                int c = i >> 6;
                int f2 = i & 63;
                float2 v = x2[i];
                float2 s = s2[i];
                u64* dst = (c & 2) ? xB : xA;
                dst[f2 * XP + (c >> 2) * 2 + (c & 1)] = PK(v.x * s.x, v.y * s.y);
            }
        }
        __syncthreads();   // B1
        if (tid < 64) {
            const u64* src = (tid & 2) ? xB : xA;
            const int off = (tid >> 2) * 2 + (tid & 1);
            u64 n2 = 0ull;
#pragma unroll 8
            for (int f2 = 0; f2 < 64; f2++) {
                u64 v = src[f2 * XP + off];
                n2 = FFMA2(v, v, n2);
            }
            invn[tid] = 1.0f / (sqrtf(HSUM(n2)) + 1e-8f);
        }
        u64 P[16], PW[8];
#pragma unroll
        for (int i = 0; i < 16; i++) P[i] = 0ull;
#pragma unroll
        for (int i = 0; i < 8; i++) PW[i] = 0ull;
#pragma unroll 2
        for (int f2 = 0; f2 < 64; f2++) {
            const int base = f2 * XP;
            ulonglong2 aA = *(const ulonglong2*)&xA[base + ty * 2];
            ulonglong2 aB = *(const ulonglong2*)&xB[base + ty * 2];
            ulonglong2 bA = *(const ulonglong2*)&xA[base + tx * 2];
            ulonglong2 bB = *(const ulonglong2*)&xB[base + tx * 2];
            ulonglong2 ww = *(const ulonglong2*)&swP[base + tx * 2];
            u64 ar0 = aA.x, ar1 = aA.y, ar2 = aB.x, ar3 = aB.y;
            u64 bc0 = bA.x, bc1 = bA.y, bc2 = bB.x, bc3 = bB.y;
            P[0]  = FFMA2(ar0, bc0, P[0]);  P[1]  = FFMA2(ar0, bc1, P[1]);
            P[2]  = FFMA2(ar0, bc2, P[2]);  P[3]  = FFMA2(ar0, bc3, P[3]);
            P[4]  = FFMA2(ar1, bc0, P[4]);  P[5]  = FFMA2(ar1, bc1, P[5]);
            P[6]  = FFMA2(ar1, bc2, P[6]);  P[7]  = FFMA2(ar1, bc3, P[7]);
            P[8]  = FFMA2(ar2, bc0, P[8]);  P[9]  = FFMA2(ar2, bc1, P[9]);
            P[10] = FFMA2(ar2, bc2, P[10]); P[11] = FFMA2(ar2, bc3, P[11]);
            P[12] = FFMA2(ar3, bc0, P[12]); P[13] = FFMA2(ar3, bc1, P[13]);
            P[14] = FFMA2(ar3, bc2, P[14]); P[15] = FFMA2(ar3, bc3, P[15]);
            PW[0] = FFMA2(ar0, ww.x, PW[0]); PW[1] = FFMA2(ar0, ww.y, PW[1]);
            PW[2] = FFMA2(ar1, ww.x, PW[2]); PW[3] = FFMA2(ar1, ww.y, PW[3]);
            PW[4] = FFMA2(ar2, ww.x, PW[4]); PW[5] = FFMA2(ar2, ww.y, PW[5]);
            PW[6] = FFMA2(ar3, ww.x, PW[6]); PW[7] = FFMA2(ar3, ww.y, PW[7]);
        }
        __syncthreads();   // B2
        {
            float* whp = g_Wh + (size_t)bt * NC * NGO + (ty * 4) * NGO + tx * 2;
#pragma unroll
            for (int r = 0; r < 4; r++)
                *(float2*)(whp + r * NGO) =
                    make_float2(HSUM(PW[r * 2]), HSUM(PW[r * 2 + 1]));
        }
        {
            float ir[4], ic[4];
#pragma unroll
            for (int i = 0; i < 4; i++) {
                ir[i] = invn[ty * 4 + i];
                ic[i] = invn[tx * 4 + i];
            }
#pragma unroll
            for (int r = 0; r < 4; r++)
#pragma unroll
                for (int c = 0; c < 4; c++)
                    accS[(r * 4 + c) * 256 + tid] += HSUM(P[r * 4 + c]) * ir[r] * ic[c];
        }
    }
    {
        float* Ab = g_A + cur_b * NC * NC;
#pragma unroll
        for (int r = 0; r < 4; r++)
#pragma unroll
            for (int c = 0; c < 4; c++)
                atomicAdd(&Ab[(ty * 4 + r) * NC + tx * 4 + c],
                          accS[(r * 4 + c) * 256 + tid]);
    }
}

// ---------------- kernel 2: top-4 + symmetrize + adjacency BITMASK ----------------
__global__ void __launch_bounds__(256) k2(void) {
    __shared__ u64 um[NC];
    const int b = blockIdx.x, tid = threadIdx.x;
    const int w = tid >> 5, lane = tid & 31;
    for (int rr = 0; rr < 8; rr++) {
        const int row = w * 8 + rr;
        const float* Ar = g_A + ((size_t)b * NC + row) * NC;
        float v0 = Ar[lane], v1 = Ar[lane + 32];
        u64 mask = 0ull;
#pragma unroll
        for (int r = 0; r < 4; r++) {
            float best; int bi;
            if (v1 > v0) { best = v1; bi = lane + 32; } else { best = v0; bi = lane; }
#pragma unroll
            for (int o = 16; o; o >>= 1) {
                float ov = __shfl_xor_sync(0xffffffffu, best, o);
                int oi = __shfl_xor_sync(0xffffffffu, bi, o);
                if (ov > best || (ov == best && oi < bi)) { best = ov; bi = oi; }
            }
            mask |= 1ull << bi;
            if (bi == lane) v0 = -3.4e38f;
            if (bi == lane + 32) v1 = -3.4e38f;
        }
        if (lane == 0) um[row] = mask & ~(1ull << row);
    }
    __syncthreads();
    if (tid < NC) {
        const int c = tid;
        const float* Ar = g_A + ((size_t)b * NC + c) * NC;
        const u64 uc = um[c];
        u64 bits = 0ull;
        for (int d = 0; d < NC; d++) {
            bool tk = (((uc >> d) | (um[d] >> c)) & 1ull) != 0;
            if (tk && Ar[d] > 0.0f) bits |= 1ull << d;
        }
        bits |= 1ull << c;   // diagonal
        g_abits[b * NC + c] = bits;
    }
}

// ---------------- kernel 3: s1/s2 + SPARSE GAT attention + node pooling ----------------
__global__ void __launch_bounds__(256) k3(const float* __restrict__ gata,
                                          const float* __restrict__ pool_w,
                                          const float* __restrict__ pool_b) {
    __shared__ float sWh[NC * 36];   // [c][j], stride 36
    __shared__ float sgat[NC * 33];
    __shared__ float ss1[NC], ss2[NC], pnum[NC];
    __shared__ float pw[NGO], sga[2 * NGO];
    __shared__ u64 sbits[NC];

    const int bt = blockIdx.x;
    const int b = bt >> 8;
    const int tid = threadIdx.x;

    const float* whg = g_Wh + (size_t)bt * NC * NGO;
    for (int i = tid; i < NC * NGO; i += 256) {
        int c = i >> 5, j = i & 31;
        sWh[c * 36 + j] = whg[i];
    }
    if (tid < NC) sbits[tid] = g_abits[b * NC + tid];
    if (tid < NGO) pw[tid] = pool_w[tid];
    if (tid < 2 * NGO) sga[tid] = gata[tid];
    __syncthreads();

    if (tid < NC) {
        float a1 = 0.0f, a2 = 0.0f;
        const float* wr = &sWh[tid * 36];
#pragma unroll 8
        for (int j = 0; j < NGO; j++) {
            float w = wr[j];
            a1 += w * sga[j];
            a2 += w * sga[NGO + j];
        }
        ss1[tid] = a1;
        ss2[tid] = a2;
    }
    __syncthreads();

    const int c = tid >> 2, q = tid & 3, j0 = q * 8;
    const float s1c = ss1[c];
    const u64 bits = sbits[c];
    float m = -3.4e38f;
    {
        u64 t = bits;
        while (t) {
            int d = __ffsll((long long)t) - 1;
            t &= t - 1;
            float e = s1c + ss2[d];
            e = (e >= 0.0f) ? e : 0.2f * e;
            m = fmaxf(m, e);
        }
    }
    float acc[8];
#pragma unroll
    for (int i = 0; i < 8; i++) acc[i] = 0.0f;
    float sum = 0.0f;
    {
        u64 t = bits;
        while (t) {
            int d = __ffsll((long long)t) - 1;
            t &= t - 1;
            float e = s1c + ss2[d];
            e = (e >= 0.0f) ? e : 0.2f * e;
            float p = __expf(e - m);
            sum += p;
            float4 w0 = *(const float4*)&sWh[d * 36 + j0];
            float4 w1 = *(const float4*)&sWh[d * 36 + j0 + 4];
            acc[0] += p * w0.x; acc[1] += p * w0.y; acc[2] += p * w0.z; acc[3] += p * w0.w;
            acc[4] += p * w1.x; acc[5] += p * w1.y; acc[6] += p * w1.z; acc[7] += p * w1.w;
        }
    }
    const float inv = 1.0f / sum;
#pragma unroll
    for (int jj = 0; jj < 8; jj++) {
        float g = acc[jj] * inv;
        sgat[c * 33 + j0 + jj] = (g > 0.0f) ? g : 0.0f;
    }
    __syncthreads();

    if (tid < NC) {
        float p = pool_b[0];
#pragma unroll
        for (int o = 0; o < NGO; o++) p += sgat[tid * 33 + o] * pw[o];
        pnum[tid] = p;
    }
    __syncthreads();
    if (tid < 32) {
        float a0 = pnum[tid], a1 = pnum[tid + 32];
        float mx = fmaxf(a0, a1);
#pragma unroll
        for (int o = 16; o; o >>= 1) mx = fmaxf(mx, __shfl_xor_sync(0xffffffffu, mx, o));
        float e0 = __expf(a0 - mx), e1 = __expf(a1 - mx);
        float sm = e0 + e1;
#pragma unroll
        for (int o = 16; o; o >>= 1) sm += __shfl_xor_sync(0xffffffffu, sm, o);
        pnum[tid] = e0 / sm;
        pnum[tid + 32] = e1 / sm;
    }
    __syncthreads();
    if (tid < NGO) {
        float hv = 0.0f;
#pragma unroll 4
        for (int c2 = 0; c2 < NC; c2++) hv += sgat[c2 * 33 + tid] * pnum[c2];
        g_hp[(size_t)bt * NH + tid] = hv;
    }
}

// ---------------- kernel 4a: LSTM input gates, Wi cached in smem ----------------
__global__ void __launch_bounds__(128) k4a(const float* __restrict__ Wi_f,
                                           const float* __restrict__ b_f,
                                           const float* __restrict__ Wi_r,
                                           const float* __restrict__ b_r) {
    __shared__ float sWi[NH * 128];
    __shared__ float hs[16 * NH];
    const int dir = blockIdx.x >> 8;
    const int grp = blockIdx.x & 255;
    const int bt0 = grp * 16;
    const int tid = threadIdx.x;
    const float* Wi = dir ? Wi_r : Wi_f;
    const float* bias = dir ? b_r : b_f;
    for (int i = tid; i < NH * 128; i += 128) sWi[i] = Wi[i];
    for (int i = tid; i < 16 * NH; i += 128) hs[i] = g_hp[(size_t)bt0 * NH + i];
    const float bj = bias[tid];
    __syncthreads();
    float* gxo = g_gx + ((size_t)dir * 4096 + bt0) * 128 + tid;
#pragma unroll 4
    for (int r = 0; r < 16; r++) {
        float a = bj;
#pragma unroll
        for (int k = 0; k < NH; k++) a += hs[r * NH + k] * sWi[k * 128 + tid];
        gxo[r * 128] = a;
    }
}

// ---------------- kernel 4b: LSTM recurrence (1 warp, k-packed gates) ----------------
__global__ void __launch_bounds__(32) k4b(const float* __restrict__ Wh_f,
                                          const float* __restrict__ Wh_r) {
    const int dir = blockIdx.x >> 4;
    const int b = blockIdx.x & 15;
    const float* Wh = dir ? Wh_r : Wh_f;
    const int j = threadIdx.x;
    u64 wi[16], wf[16], wg[16], wo[16];
#pragma unroll
    for (int kp = 0; kp < 16; kp++) {
        const float* ra = Wh + (2 * kp) * 128;
        const float* rb = Wh + (2 * kp + 1) * 128;
        wi[kp] = PK(ra[j],      rb[j]);
        wf[kp] = PK(ra[j + 32], rb[j + 32]);
        wg[kp] = PK(ra[j + 64], rb[j + 64]);
        wo[kp] = PK(ra[j + 96], rb[j + 96]);
    }
    const float* gx = g_gx + ((size_t)dir * 4096 + b * NT) * 128;
    float h = 0.0f, cst = 0.0f;
    int t = dir ? (NT - 1) : 0;
    const int st = dir ? -1 : 1;
    const float* g0p = gx + t * 128;
    float c0 = g0p[j], c1 = g0p[j + 32], c2 = g0p[j + 64], c3 = g0p[j + 96];
    for (int s = 0; s < NT; s++) {
        const int tn = t + st;
        float n0 = 0.0f, n1 = 0.0f, n2 = 0.0f, n3 = 0.0f;
        if (s < NT - 1) {
            const float* gn = gx + tn * 128;
            n0 = gn[j]; n1 = gn[j + 32]; n2 = gn[j + 64]; n3 = gn[j + 96];
        }
        u64 ai = 0ull, af = 0ull, ag = 0ull, ao = 0ull;
#pragma unroll
        for (int kp = 0; kp < 16; kp++) {
            float h0 = __shfl_sync(0xffffffffu, h, 2 * kp);
            float h1 = __shfl_sync(0xffffffffu, h, 2 * kp + 1);
            u64 hp = PK(h0, h1);
            ai = FFMA2(hp, wi[kp], ai);
            af = FFMA2(hp, wf[kp], af);
            ag = FFMA2(hp, wg[kp], ag);
            ao = FFMA2(hp, wo[kp], ao);
        }
        float gi = c0 + HSUM(ai), gf = c1 + HSUM(af);
        float gg = c2 + HSUM(ag), go = c3 + HSUM(ao);
        float ig = fast_sig(gi), fg = fast_sig(gf), og = fast_sig(go);
        cst = fg * cst + ig * fast_tanh(gg);
        h = og * fast_tanh(cst);
        g_hl[(size_t)(b * NT + t) * 64 + dir * NH + j] = h;
        c0 = n0; c1 = n1; c2 = n2; c3 = n3;
        t = tn;
    }
}

// ---------------- kernel 5a: temporal attention scores (16x parallel) ----------------
// grid NB*16 = 256 blocks; block = (b, 16 timesteps); threads = (t_local, jj-group)
__global__ void __launch_bounds__(256) k5a(const float* __restrict__ taW,
                                           const float* __restrict__ tab,
                                           const float* __restrict__ tav) {
    __shared__ __align__(16) float sWt[64 * 68];   // [jj][k] transposed
    __shared__ __align__(16) float sh[16 * 68];    // h rows for 16 timesteps
    __shared__ float stb[64], stv[64];
    const int tid = threadIdx.x;
    const int b = blockIdx.x >> 4;
    const int t0 = (blockIdx.x & 15) * 16;
    for (int i = tid; i < 4096; i += 256) {
        int k = i >> 6, jj = i & 63;
        sWt[jj * 68 + k] = taW[i];
    }
    for (int i = tid; i < 16 * 64; i += 256) {
        int tl = i >> 6, k = i & 63;
        sh[tl * 68 + k] = g_hl[(size_t)(b * NT + t0 + tl) * 64 + k];
    }
    if (tid < 64) { stb[tid] = tab[tid]; stv[tid] = tav[tid]; }
    __syncthreads();
    const int tl = tid >> 4, jg = tid & 15;
    const float* hrow = &sh[tl * 68];
    float sc = 0.0f;
#pragma unroll
    for (int u = 0; u < 4; u++) {
        const int jj = jg * 4 + u;
        const float* wr = &sWt[jj * 68];
        u64 a0 = PK(stb[jj], 0.0f), a1 = 0ull;
#pragma unroll
        for (int k = 0; k < 64; k += 4) {
            ulonglong2 hv = *(const ulonglong2*)&hrow[k];
            ulonglong2 wv = *(const ulonglong2*)&wr[k];
            a0 = FFMA2(hv.x, wv.x, a0);
            a1 = FFMA2(hv.y, wv.y, a1);
        }
        sc += fast_tanh(HSUM(a0) + HSUM(a1)) * stv[jj];
    }
    // reduce over jg (lane bits 0..3)
#pragma unroll
    for (int o = 8; o; o >>= 1) sc += __shfl_xor_sync(0xffffffffu, sc, o);
    if (jg == 0) g_sc[b * NT + t0 + tl] = sc * (1.0f / 1.5f);
}

// ---------------- kernel 5b: softmax + ctx + LN + MLP head ----------------
__global__ void k5b(const float* __restrict__ lng, const float* __restrict__ lnb,
                    const float* __restrict__ f1w, const float* __restrict__ f1b,
                    const float* __restrict__ f2w, const float* __restrict__ f2b,
                    float* __restrict__ out) {
    const int b = blockIdx.x, t = threadIdx.x;
    __shared__ float sal[NT];
    __shared__ float wr[8];
    __shared__ float part[4][64];
    __shared__ float ctxs[64];
    __shared__ float y1s[32];
    __shared__ float stats[2];
    float sc = g_sc[b * NT + t];
    const int lane = t & 31, w = t >> 5;
    float m = sc;
#pragma unroll
    for (int o = 16; o; o >>= 1) m = fmaxf(m, __shfl_xor_sync(0xffffffffu, m, o));
    if (lane == 0) wr[w] = m;
    __syncthreads();
    m = wr[0];
#pragma unroll
    for (int i = 1; i < 8; i++) m = fmaxf(m, wr[i]);
    float e = __expf(sc - m);
    float s = e;
#pragma unroll
    for (int o = 16; o; o >>= 1) s += __shfl_xor_sync(0xffffffffu, s, o);
    __syncthreads();
    if (lane == 0) wr[w] = s;
    __syncthreads();
    s = 0.0f;
#pragma unroll
    for (int i = 0; i < 8; i++) s += wr[i];
    sal[t] = e / s;
    __syncthreads();
    {
        const int k = t & 63, q4 = t >> 6;
        float cx = 0.0f;
        const float* hb = g_hl + (size_t)b * NT * 64;
        for (int tt = q4 * 64; tt < q4 * 64 + 64; tt++)
            cx += hb[(size_t)tt * 64 + k] * sal[tt];
        part[q4][k] = cx;
    }
    __syncthreads();
    if (t < 64) ctxs[t] = part[0][t] + part[1][t] + part[2][t] + part[3][t];
    __syncthreads();
    if (t == 0) {
        float mean = 0.0f;
        for (int k = 0; k < 64; k++) mean += ctxs[k];
        mean *= (1.0f / 64.0f);
        float var = 0.0f;
        for (int k = 0; k < 64; k++) { float d2 = ctxs[k] - mean; var += d2 * d2; }
        var *= (1.0f / 64.0f);
        stats[0] = mean;
        stats[1] = rsqrtf(var + 1e-5f);
    }
    __syncthreads();
    if (t < 64) ctxs[t] = (ctxs[t] - stats[0]) * stats[1] * lng[t] + lnb[t];
    __syncthreads();
    if (t < 32) {
        float a = f1b[t];
#pragma unroll
        for (int k = 0; k < 64; k++) a += ctxs[k] * f1w[k * 32 + t];
        y1s[t] = (a > 0.0f) ? a : 0.0f;
    }
    __syncthreads();
    if (t < 3) {
        float o = f2b[t];
#pragma unroll
        for (int m2 = 0; m2 < 32; m2++) o += y1s[m2] * f2w[m2 * 3 + t];
        out[b * 3 + t] = o;
    }
}

// ---------------- launcher ----------------
extern "C" void kernel_launch(void* const* d_in, const int* in_sizes, int n_in,
                              void* d_out, int out_size) {
    const float* x       = (const float*)d_in[0];
    const float* spec_w  = (const float*)d_in[1];
    const float* gat_W   = (const float*)d_in[2];
    const float* gat_a   = (const float*)d_in[3];
    const float* pool_w  = (const float*)d_in[4];
    const float* pool_b  = (const float*)d_in[5];
    const float* Wi_f    = (const float*)d_in[6];
    const float* Wh_f    = (const float*)d_in[7];
    const float* b_f     = (const float*)d_in[8];
    const float* Wi_r    = (const float*)d_in[9];
    const float* Wh_r    = (const float*)d_in[10];
    const float* b_r     = (const float*)d_in[11];
    const float* taW     = (const float*)d_in[12];
    const float* tab     = (const float*)d_in[13];
    const float* tav     = (const float*)d_in[14];
    const float* lng     = (const float*)d_in[15];
    const float* lnb     = (const float*)d_in[16];
    const float* f1w     = (const float*)d_in[17];
    const float* f1b     = (const float*)d_in[18];
    const float* f2w     = (const float*)d_in[19];
    const float* f2b     = (const float*)d_in[20];

    const int kG_smem = (3 * 64 * XP + 32) * 8 + 16 * 256 * 4;
    cudaFuncSetAttribute(kGW, cudaFuncAttributeMaxDynamicSharedMemorySize, kG_smem);

    k_sm<<<64, 128>>>(spec_w);                        // launch 1 (also zeros g_A)
    kGW<<<GGRID, 256, kG_smem>>>(x, gat_W);           // launch 2
    k2<<<NB, 256>>>();                                // launch 3
    k3<<<NB * NT, 256>>>(gat_a, pool_w, pool_b);      // launch 4 <- profiled
    k4a<<<512, 128>>>(Wi_f, b_f, Wi_r, b_r);
    k4b<<<32, 32>>>(Wh_f, Wh_r);
    k5a<<<NB * 16, 256>>>(taW, tab, tav);
    k5b<<<NB, 256>>>(lng, lnb, f1w, f1b, f2w, f2b, (float*)d_out);
}

// round 15
// speedup vs baseline: 1.0124x; 1.0124x over previous
#include <cuda_runtime.h>
#include <math.h>

#define NB 16
#define NT 256
#define NC 64
#define NF 128
#define NGO 32
#define NH 32
#define XP 34    // u64 row stride for 32-slot paired smem arrays
#define GGRID 456  // kGW grid: 3 blocks/SM x 152 SMs, single wave

typedef unsigned long long u64;

// ---------------- packed f32x2 helpers ----------------
__device__ __forceinline__ u64 PK(float x, float y) {
    u64 r;
    asm("mov.b64 %0, {%1,%2};" : "=l"(r) : "f"(x), "f"(y));
    return r;
}
__device__ __forceinline__ float2 UPK(u64 v) {
    float2 f;
    asm("mov.b64 {%0,%1}, %2;" : "=f"(f.x), "=f"(f.y) : "l"(v));
    return f;
}
__device__ __forceinline__ u64 FFMA2(u64 a, u64 b, u64 c) {
    u64 d;
    asm("fma.rn.f32x2 %0, %1, %2, %3;" : "=l"(d) : "l"(a), "l"(b), "l"(c));
    return d;
}
__device__ __forceinline__ float HSUM(u64 v) {
    float2 f = UPK(v);
    return f.x + f.y;
}
__device__ __forceinline__ float fast_tanh(float x) {
    float e = __expf(2.0f * x);
    return 1.0f - __fdividef(2.0f, e + 1.0f);
}
__device__ __forceinline__ float fast_sig(float x) {
    return 1.0f / (1.0f + __expf(-x));
}

// ---------------- scratch ----------------
__device__ float g_sm[NC * NF];
__device__ float g_A[NB * NC * NC];
__device__ u64 g_abits[NB * NC];             // adjacency bitmask per row
__device__ float g_Wh[NB * NT * NC * NGO];   // [bt][c][j]
__device__ float g_hp[NB * NT * NH];
__device__ float g_gx[2 * NB * NT * 4 * NH];
__device__ float g_hl[NB * NT * 2 * NH];
__device__ float g_sc[NB * NT];

// ---------------- kernel 0: zero A + row softmax of spectral_w ----------------
__global__ void k_sm(const float* __restrict__ sw) {
    int c = blockIdx.x, f = threadIdx.x;
    {
        int base = blockIdx.x * 1024;
#pragma unroll
        for (int i = threadIdx.x; i < 1024; i += 128) g_A[base + i] = 0.0f;
    }
    float v = sw[c * NF + f];
    __shared__ float rm[4], rs[4];
    int lane = f & 31, w = f >> 5;
    float m = v;
#pragma unroll
    for (int o = 16; o; o >>= 1) m = fmaxf(m, __shfl_xor_sync(0xffffffffu, m, o));
    if (lane == 0) rm[w] = m;
    __syncthreads();
    m = fmaxf(fmaxf(rm[0], rm[1]), fmaxf(rm[2], rm[3]));
    float e = __expf(v - m);
    float s = e;
#pragma unroll
    for (int o = 16; o; o >>= 1) s += __shfl_xor_sync(0xffffffffu, s, o);
    if (lane == 0) rs[w] = s;
    __syncthreads();
    s = rs[0] + rs[1] + rs[2] + rs[3];
    g_sm[c * NF + f] = e / s;
}

// ---------------- kernel GW: Gram 8x4 + Wh 8x2 per thread, 128 threads ----------------
// Per f2 per thread: 7 LDS.128 feed 48 FFMA2 (32 Gram + 16 Wh).
extern __shared__ u64 shG[];
__global__ void __launch_bounds__(128, 3) kGW(const float* __restrict__ x,
                                              const float* __restrict__ gatW) {
    u64* xA  = shG;                      // [64][XP]
    u64* xB  = shG + 64 * XP;            // [64][XP]
    u64* swP = shG + 2 * 64 * XP;        // [64 f2][XP slots j]
    float* invn = (float*)(shG + 3 * 64 * XP);           // [64]
    float* accS = (float*)(shG + 3 * 64 * XP + 32);      // [32][128] per-thread acc

    const int tid = threadIdx.x;
    const int ty = tid >> 4;        // 0..7  -> 8 gram rows ty*8..+7
    const int tx = tid & 15;        // 0..15 -> 4 gram cols tx*4..+3; Wh cols 2tx,2tx+1

    const int bid = blockIdx.x;
    const int sIt = (bid * (NB * NT)) / GGRID;
    const int eIt = ((bid + 1) * (NB * NT)) / GGRID;

    for (int i = tid; i < 64 * NGO; i += 128) {
        int f2 = i >> 5, j = i & 31;
        swP[f2 * XP + j] = PK(gatW[(2 * f2) * NGO + j], gatW[(2 * f2 + 1) * NGO + j]);
    }
#pragma unroll
    for (int i = 0; i < 32; i++) accS[i * 128 + tid] = 0.0f;

    int cur_b = sIt >> 8;
    for (int bt = sIt; bt < eIt; bt++) {
        const int b = bt >> 8;
        if (b != cur_b) {
            float* Ab = g_A + cur_b * NC * NC;
#pragma unroll
            for (int r = 0; r < 8; r++)
#pragma unroll
                for (int c = 0; c < 4; c++) {
                    atomicAdd(&Ab[(ty * 8 + r) * NC + tx * 4 + c],
                              accS[(r * 4 + c) * 128 + tid]);
                    accS[(r * 4 + c) * 128 + tid] = 0.0f;
                }
            cur_b = b;
        }
        // load + spectral scale into split layout (coalesced)
        {
            const float2* x2 = (const float2*)(x + (size_t)bt * NC * NF);
            const float2* s2 = (const float2*)g_sm;
            for (int i = tid; i < NC * NF / 2; i += 128) {
                int c = i >> 6;
                int f2 = i & 63;
                float2 v = x2[i];
                float2 s = s2[i];
                u64* dst = (c & 2) ? xB : xA;
                dst[f2 * XP + (c >> 2) * 2 + (c & 1)] = PK(v.x * s.x, v.y * s.y);
            }
        }
        __syncthreads();   // B1: tile ready (covers swP/accS init on first iter)
        // norms (threads 0..63)
        if (tid < 64) {
            const u64* src = (tid & 2) ? xB : xA;
            const int off = (tid >> 2) * 2 + (tid & 1);
            u64 n2 = 0ull;
#pragma unroll 8
            for (int f2 = 0; f2 < 64; f2++) {
                u64 v = src[f2 * XP + off];
                n2 = FFMA2(v, v, n2);
            }
            invn[tid] = 1.0f / (sqrtf(HSUM(n2)) + 1e-8f);
        }
        // fused Gram 8x4 + Wh 8x2 loop
        u64 P[32], PW[16];
#pragma unroll
        for (int i = 0; i < 32; i++) P[i] = 0ull;
#pragma unroll
        for (int i = 0; i < 16; i++) PW[i] = 0ull;
        for (int f2 = 0; f2 < 64; f2++) {
            const int base = f2 * XP;
            // a rows: channels ty*8..+7 -> order [A01.x,A01.y,B01.x,B01.y,A23.x,A23.y,B23.x,B23.y]
            ulonglong2 aA01 = *(const ulonglong2*)&xA[base + ty * 4];
            ulonglong2 aB01 = *(const ulonglong2*)&xB[base + ty * 4];
            ulonglong2 aA23 = *(const ulonglong2*)&xA[base + ty * 4 + 2];
            ulonglong2 aB23 = *(const ulonglong2*)&xB[base + ty * 4 + 2];
            // b cols: channels tx*4..+3
            ulonglong2 bA = *(const ulonglong2*)&xA[base + tx * 2];
            ulonglong2 bB = *(const ulonglong2*)&xB[base + tx * 2];
            // Wh weights: cols 2tx, 2tx+1
            ulonglong2 ww = *(const ulonglong2*)&swP[base + tx * 2];
            u64 ar[8];
            ar[0] = aA01.x; ar[1] = aA01.y; ar[2] = aB01.x; ar[3] = aB01.y;
            ar[4] = aA23.x; ar[5] = aA23.y; ar[6] = aB23.x; ar[7] = aB23.y;
            u64 bc0 = bA.x, bc1 = bA.y, bc2 = bB.x, bc3 = bB.y;
#pragma unroll
            for (int r = 0; r < 8; r++) {
                P[r * 4 + 0] = FFMA2(ar[r], bc0, P[r * 4 + 0]);
                P[r * 4 + 1] = FFMA2(ar[r], bc1, P[r * 4 + 1]);
                P[r * 4 + 2] = FFMA2(ar[r], bc2, P[r * 4 + 2]);
                P[r * 4 + 3] = FFMA2(ar[r], bc3, P[r * 4 + 3]);
                PW[r * 2 + 0] = FFMA2(ar[r], ww.x, PW[r * 2 + 0]);
                PW[r * 2 + 1] = FFMA2(ar[r], ww.y, PW[r * 2 + 1]);
            }
        }
        __syncthreads();   // B2: invn ready; all tile reads done before next load
        // Wh store: thread -> rows ty*8+r, cols 2tx, 2tx+1
        {
            float* whp = g_Wh + (size_t)bt * NC * NGO + (ty * 8) * NGO + tx * 2;
#pragma unroll
            for (int r = 0; r < 8; r++)
                *(float2*)(whp + r * NGO) =
                    make_float2(HSUM(PW[r * 2]), HSUM(PW[r * 2 + 1]));
        }
        // acc update (smem, lane-stride conflict-free)
        {
            float ir[8], ic[4];
#pragma unroll
            for (int i = 0; i < 8; i++) ir[i] = invn[ty * 8 + i];
#pragma unroll
            for (int i = 0; i < 4; i++) ic[i] = invn[tx * 4 + i];
#pragma unroll
            for (int r = 0; r < 8; r++)
#pragma unroll
                for (int c = 0; c < 4; c++)
                    accS[(r * 4 + c) * 128 + tid] += HSUM(P[r * 4 + c]) * ir[r] * ic[c];
        }
    }
    // final flush
    {
        float* Ab = g_A + cur_b * NC * NC;
#pragma unroll
        for (int r = 0; r < 8; r++)
#pragma unroll
            for (int c = 0; c < 4; c++)
                atomicAdd(&Ab[(ty * 8 + r) * NC + tx * 4 + c],
                          accS[(r * 4 + c) * 128 + tid]);
    }
}

// ---------------- kernel 2: top-4 + symmetrize + adjacency BITMASK ----------------
__global__ void __launch_bounds__(256) k2(void) {
    __shared__ u64 um[NC];
    const int b = blockIdx.x, tid = threadIdx.x;
    const int w = tid >> 5, lane = tid & 31;
    for (int rr = 0; rr < 8; rr++) {
        const int row = w * 8 + rr;
        const float* Ar = g_A + ((size_t)b * NC + row) * NC;
        float v0 = Ar[lane], v1 = Ar[lane + 32];
        u64 mask = 0ull;
#pragma unroll
        for (int r = 0; r < 4; r++) {
            float best; int bi;
            if (v1 > v0) { best = v1; bi = lane + 32; } else { best = v0; bi = lane; }
#pragma unroll
            for (int o = 16; o; o >>= 1) {
                float ov = __shfl_xor_sync(0xffffffffu, best, o);
                int oi = __shfl_xor_sync(0xffffffffu, bi, o);
                if (ov > best || (ov == best && oi < bi)) { best = ov; bi = oi; }
            }
            mask |= 1ull << bi;
            if (bi == lane) v0 = -3.4e38f;
            if (bi == lane + 32) v1 = -3.4e38f;
        }
        if (lane == 0) um[row] = mask & ~(1ull << row);
    }
    __syncthreads();
    if (tid < NC) {
        const int c = tid;
        const float* Ar = g_A + ((size_t)b * NC + c) * NC;
        const u64 uc = um[c];
        u64 bits = 0ull;
        for (int d = 0; d < NC; d++) {
            bool tk = (((uc >> d) | (um[d] >> c)) & 1ull) != 0;
            if (tk && Ar[d] > 0.0f) bits |= 1ull << d;
        }
        bits |= 1ull << c;   // diagonal
        g_abits[b * NC + c] = bits;
    }
}

// ---------------- kernel 3: s1/s2 + SPARSE GAT attention + node pooling ----------------
__global__ void __launch_bounds__(256) k3(const float* __restrict__ gata,
                                          const float* __restrict__ pool_w,
                                          const float* __restrict__ pool_b) {
    __shared__ float sWh[NC * 36];   // [c][j], stride 36
    __shared__ float sgat[NC * 33];
    __shared__ float ss1[NC], ss2[NC], pnum[NC];
    __shared__ float pw[NGO], sga[2 * NGO];
    __shared__ u64 sbits[NC];

    const int bt = blockIdx.x;
    const int b = bt >> 8;
    const int tid = threadIdx.x;

    const float* whg = g_Wh + (size_t)bt * NC * NGO;
    for (int i = tid; i < NC * NGO; i += 256) {
        int c = i >> 5, j = i & 31;
        sWh[c * 36 + j] = whg[i];
    }
    if (tid < NC) sbits[tid] = g_abits[b * NC + tid];
    if (tid < NGO) pw[tid] = pool_w[tid];
    if (tid < 2 * NGO) sga[tid] = gata[tid];
    __syncthreads();

    if (tid < NC) {
        float a1 = 0.0f, a2 = 0.0f;
        const float* wr = &sWh[tid * 36];
#pragma unroll 8
        for (int j = 0; j < NGO; j++) {
            float w = wr[j];
            a1 += w * sga[j];
            a2 += w * sga[NGO + j];
        }
        ss1[tid] = a1;
        ss2[tid] = a2;
    }
    __syncthreads();

    const int c = tid >> 2, q = tid & 3, j0 = q * 8;
    const float s1c = ss1[c];
    const u64 bits = sbits[c];
    float m = -3.4e38f;
    {
        u64 t = bits;
        while (t) {
            int d = __ffsll((long long)t) - 1;
            t &= t - 1;
            float e = s1c + ss2[d];
            e = (e >= 0.0f) ? e : 0.2f * e;
            m = fmaxf(m, e);
        }
    }
    float acc[8];
#pragma unroll
    for (int i = 0; i < 8; i++) acc[i] = 0.0f;
    float sum = 0.0f;
    {
        u64 t = bits;
        while (t) {
            int d = __ffsll((long long)t) - 1;
            t &= t - 1;
            float e = s1c + ss2[d];
            e = (e >= 0.0f) ? e : 0.2f * e;
            float p = __expf(e - m);
            sum += p;
            float4 w0 = *(const float4*)&sWh[d * 36 + j0];
            float4 w1 = *(const float4*)&sWh[d * 36 + j0 + 4];
            acc[0] += p * w0.x; acc[1] += p * w0.y; acc[2] += p * w0.z; acc[3] += p * w0.w;
            acc[4] += p * w1.x; acc[5] += p * w1.y; acc[6] += p * w1.z; acc[7] += p * w1.w;
        }
    }
    const float inv = 1.0f / sum;
#pragma unroll
    for (int jj = 0; jj < 8; jj++) {
        float g = acc[jj] * inv;
        sgat[c * 33 + j0 + jj] = (g > 0.0f) ? g : 0.0f;
    }
    __syncthreads();

    if (tid < NC) {
        float p = pool_b[0];
#pragma unroll
        for (int o = 0; o < NGO; o++) p += sgat[tid * 33 + o] * pw[o];
        pnum[tid] = p;
    }
    __syncthreads();
    if (tid < 32) {
        float a0 = pnum[tid], a1 = pnum[tid + 32];
        float mx = fmaxf(a0, a1);
#pragma unroll
        for (int o = 16; o; o >>= 1) mx = fmaxf(mx, __shfl_xor_sync(0xffffffffu, mx, o));
        float e0 = __expf(a0 - mx), e1 = __expf(a1 - mx);
        float sm = e0 + e1;
#pragma unroll
        for (int o = 16; o; o >>= 1) sm += __shfl_xor_sync(0xffffffffu, sm, o);
        pnum[tid] = e0 / sm;
        pnum[tid + 32] = e1 / sm;
    }
    __syncthreads();
    if (tid < NGO) {
        float hv = 0.0f;
#pragma unroll 4
        for (int c2 = 0; c2 < NC; c2++) hv += sgat[c2 * 33 + tid] * pnum[c2];
        g_hp[(size_t)bt * NH + tid] = hv;
    }
}

// ---------------- kernel 4a: LSTM input gates, Wi cached in smem ----------------
__global__ void __launch_bounds__(128) k4a(const float* __restrict__ Wi_f,
                                           const float* __restrict__ b_f,
                                           const float* __restrict__ Wi_r,
                                           const float* __restrict__ b_r) {
    __shared__ float sWi[NH * 128];
    __shared__ float hs[16 * NH];
    const int dir = blockIdx.x >> 8;
    const int grp = blockIdx.x & 255;
    const int bt0 = grp * 16;
    const int tid = threadIdx.x;
    const float* Wi = dir ? Wi_r : Wi_f;
    const float* bias = dir ? b_r : b_f;
    for (int i = tid; i < NH * 128; i += 128) sWi[i] = Wi[i];
    for (int i = tid; i < 16 * NH; i += 128) hs[i] = g_hp[(size_t)bt0 * NH + i];
    const float bj = bias[tid];
    __syncthreads();
    float* gxo = g_gx + ((size_t)dir * 4096 + bt0) * 128 + tid;
#pragma unroll 4
    for (int r = 0; r < 16; r++) {
        float a = bj;
#pragma unroll
        for (int k = 0; k < NH; k++) a += hs[r * NH + k] * sWi[k * 128 + tid];
        gxo[r * 128] = a;
    }
}

// ---------------- kernel 4b: LSTM recurrence (1 warp, k-packed gates) ----------------
__global__ void __launch_bounds__(32) k4b(const float* __restrict__ Wh_f,
                                          const float* __restrict__ Wh_r) {
    const int dir = blockIdx.x >> 4;
    const int b = blockIdx.x & 15;
    const float* Wh = dir ? Wh_r : Wh_f;
    const int j = threadIdx.x;
    u64 wi[16], wf[16], wg[16], wo[16];
#pragma unroll
    for (int kp = 0; kp < 16; kp++) {
        const float* ra = Wh + (2 * kp) * 128;
        const float* rb = Wh + (2 * kp + 1) * 128;
        wi[kp] = PK(ra[j],      rb[j]);
        wf[kp] = PK(ra[j + 32], rb[j + 32]);
        wg[kp] = PK(ra[j + 64], rb[j + 64]);
        wo[kp] = PK(ra[j + 96], rb[j + 96]);
    }
    const float* gx = g_gx + ((size_t)dir * 4096 + b * NT) * 128;
    float h = 0.0f, cst = 0.0f;
    int t = dir ? (NT - 1) : 0;
    const int st = dir ? -1 : 1;
    const float* g0p = gx + t * 128;
    float c0 = g0p[j], c1 = g0p[j + 32], c2 = g0p[j + 64], c3 = g0p[j + 96];
    for (int s = 0; s < NT; s++) {
        const int tn = t + st;
        float n0 = 0.0f, n1 = 0.0f, n2 = 0.0f, n3 = 0.0f;
        if (s < NT - 1) {
            const float* gn = gx + tn * 128;
            n0 = gn[j]; n1 = gn[j + 32]; n2 = gn[j + 64]; n3 = gn[j + 96];
        }
        u64 ai = 0ull, af = 0ull, ag = 0ull, ao = 0ull;
#pragma unroll
        for (int kp = 0; kp < 16; kp++) {
            float h0 = __shfl_sync(0xffffffffu, h, 2 * kp);
            float h1 = __shfl_sync(0xffffffffu, h, 2 * kp + 1);
            u64 hp = PK(h0, h1);
            ai = FFMA2(hp, wi[kp], ai);
            af = FFMA2(hp, wf[kp], af);
            ag = FFMA2(hp, wg[kp], ag);
            ao = FFMA2(hp, wo[kp], ao);
        }
        float gi = c0 + HSUM(ai), gf = c1 + HSUM(af);
        float gg = c2 + HSUM(ag), go = c3 + HSUM(ao);
        float ig = fast_sig(gi), fg = fast_sig(gf), og = fast_sig(go);
        cst = fg * cst + ig * fast_tanh(gg);
        h = og * fast_tanh(cst);
        g_hl[(size_t)(b * NT + t) * 64 + dir * NH + j] = h;
        c0 = n0; c1 = n1; c2 = n2; c3 = n3;
        t = tn;
    }
}

// ---------------- kernel 5a: temporal attention scores (16x parallel) ----------------
__global__ void __launch_bounds__(256) k5a(const float* __restrict__ taW,
                                           const float* __restrict__ tab,
                                           const float* __restrict__ tav) {
    __shared__ __align__(16) float sWt[64 * 68];   // [jj][k] transposed
    __shared__ __align__(16) float sh[16 * 68];    // h rows for 16 timesteps
    __shared__ float stb[64], stv[64];
    const int tid = threadIdx.x;
    const int b = blockIdx.x >> 4;
    const int t0 = (blockIdx.x & 15) * 16;
    for (int i = tid; i < 4096; i += 256) {
        int k = i >> 6, jj = i & 63;
        sWt[jj * 68 + k] = taW[i];
    }
    for (int i = tid; i < 16 * 64; i += 256) {
        int tl = i >> 6, k = i & 63;
        sh[tl * 68 + k] = g_hl[(size_t)(b * NT + t0 + tl) * 64 + k];
    }
    if (tid < 64) { stb[tid] = tab[tid]; stv[tid] = tav[tid]; }
    __syncthreads();
    const int tl = tid >> 4, jg = tid & 15;
    const float* hrow = &sh[tl * 68];
    float sc = 0.0f;
#pragma unroll
    for (int u = 0; u < 4; u++) {
        const int jj = jg * 4 + u;
        const float* wr = &sWt[jj * 68];
        u64 a0 = PK(stb[jj], 0.0f), a1 = 0ull;
#pragma unroll
        for (int k = 0; k < 64; k += 4) {
            ulonglong2 hv = *(const ulonglong2*)&hrow[k];
            ulonglong2 wv = *(const ulonglong2*)&wr[k];
            a0 = FFMA2(hv.x, wv.x, a0);
            a1 = FFMA2(hv.y, wv.y, a1);
        }
        sc += fast_tanh(HSUM(a0) + HSUM(a1)) * stv[jj];
    }
#pragma unroll
    for (int o = 8; o; o >>= 1) sc += __shfl_xor_sync(0xffffffffu, sc, o);
    if (jg == 0) g_sc[b * NT + t0 + tl] = sc * (1.0f / 1.5f);
}

// ---------------- kernel 5b: softmax + ctx + LN + MLP head ----------------
__global__ void k5b(const float* __restrict__ lng, const float* __restrict__ lnb,
                    const float* __restrict__ f1w, const float* __restrict__ f1b,
                    const float* __restrict__ f2w, const float* __restrict__ f2b,
                    float* __restrict__ out) {
    const int b = blockIdx.x, t = threadIdx.x;
    __shared__ float sal[NT];
    __shared__ float wr[8];
    __shared__ float part[4][64];
    __shared__ float ctxs[64];
    __shared__ float y1s[32];
    __shared__ float stats[2];
    float sc = g_sc[b * NT + t];
    const int lane = t & 31, w = t >> 5;
    float m = sc;
#pragma unroll
    for (int o = 16; o; o >>= 1) m = fmaxf(m, __shfl_xor_sync(0xffffffffu, m, o));
    if (lane == 0) wr[w] = m;
    __syncthreads();
    m = wr[0];
#pragma unroll
    for (int i = 1; i < 8; i++) m = fmaxf(m, wr[i]);
    float e = __expf(sc - m);
    float s = e;
#pragma unroll
    for (int o = 16; o; o >>= 1) s += __shfl_xor_sync(0xffffffffu, s, o);
    __syncthreads();
    if (lane == 0) wr[w] = s;
    __syncthreads();
    s = 0.0f;
#pragma unroll
    for (int i = 0; i < 8; i++) s += wr[i];
    sal[t] = e / s;
    __syncthreads();
    {
        const int k = t & 63, q4 = t >> 6;
        float cx = 0.0f;
        const float* hb = g_hl + (size_t)b * NT * 64;
        for (int tt = q4 * 64; tt < q4 * 64 + 64; tt++)
            cx += hb[(size_t)tt * 64 + k] * sal[tt];
        part[q4][k] = cx;
    }
    __syncthreads();
    if (t < 64) ctxs[t] = part[0][t] + part[1][t] + part[2][t] + part[3][t];
    __syncthreads();
    if (t == 0) {
        float mean = 0.0f;
        for (int k = 0; k < 64; k++) mean += ctxs[k];
        mean *= (1.0f / 64.0f);
        float var = 0.0f;
        for (int k = 0; k < 64; k++) { float d2 = ctxs[k] - mean; var += d2 * d2; }
        var *= (1.0f / 64.0f);
        stats[0] = mean;
        stats[1] = rsqrtf(var + 1e-5f);
    }
    __syncthreads();
    if (t < 64) ctxs[t] = (ctxs[t] - stats[0]) * stats[1] * lng[t] + lnb[t];
    __syncthreads();
    if (t < 32) {
        float a = f1b[t];
#pragma unroll
        for (int k = 0; k < 64; k++) a += ctxs[k] * f1w[k * 32 + t];
        y1s[t] = (a > 0.0f) ? a : 0.0f;
    }
    __syncthreads();
    if (t < 3) {
        float o = f2b[t];
#pragma unroll
        for (int m2 = 0; m2 < 32; m2++) o += y1s[m2] * f2w[m2 * 3 + t];
        out[b * 3 + t] = o;
    }
}

// ---------------- launcher ----------------
extern "C" void kernel_launch(void* const* d_in, const int* in_sizes, int n_in,
                              void* d_out, int out_size) {
    const float* x       = (const float*)d_in[0];
    const float* spec_w  = (const float*)d_in[1];
    const float* gat_W   = (const float*)d_in[2];
    const float* gat_a   = (const float*)d_in[3];
    const float* pool_w  = (const float*)d_in[4];
    const float* pool_b  = (const float*)d_in[5];
    const float* Wi_f    = (const float*)d_in[6];
    const float* Wh_f    = (const float*)d_in[7];
    const float* b_f     = (const float*)d_in[8];
    const float* Wi_r    = (const float*)d_in[9];
    const float* Wh_r    = (const float*)d_in[10];
    const float* b_r     = (const float*)d_in[11];
    const float* taW     = (const float*)d_in[12];
    const float* tab     = (const float*)d_in[13];
    const float* tav     = (const float*)d_in[14];
    const float* lng     = (const float*)d_in[15];
    const float* lnb     = (const float*)d_in[16];
    const float* f1w     = (const float*)d_in[17];
    const float* f1b     = (const float*)d_in[18];
    const float* f2w     = (const float*)d_in[19];
    const float* f2b     = (const float*)d_in[20];

    // smem: xA+xB+swP (3*64*XP u64) + invn pad (32 u64) + accS (32*128 f)
    const int kG_smem = (3 * 64 * XP + 32) * 8 + 32 * 128 * 4;   // 68864 B
    cudaFuncSetAttribute(kGW, cudaFuncAttributeMaxDynamicSharedMemorySize, kG_smem);

    k_sm<<<64, 128>>>(spec_w);                        // launch 1 (also zeros g_A)
    kGW<<<GGRID, 128, kG_smem>>>(x, gat_W);           // launch 2
    k2<<<NB, 256>>>();                                // launch 3
    k3<<<NB * NT, 256>>>(gat_a, pool_w, pool_b);      // launch 4 <- profiled
    k4a<<<512, 128>>>(Wi_f, b_f, Wi_r, b_r);
    k4b<<<32, 32>>>(Wh_f, Wh_r);
    k5a<<<NB * 16, 256>>>(taW, tab, tav);
    k5b<<<NB, 256>>>(lng, lnb, f1w, f1b, f2w, f2b, (float*)d_out);
}

// round 16
// speedup vs baseline: 1.0252x; 1.0126x over previous
#include <cuda_runtime.h>
#include <math.h>

#define NB 16
#define NT 256
#define NC 64
#define NF 128
#define NGO 32
#define NH 32
#define XP 34    // u64 row stride for 32-slot paired smem arrays
#define GGRID 456  // kGW grid: 3 blocks/SM x 152 SMs, single wave

typedef unsigned long long u64;

// ---------------- packed f32x2 helpers ----------------
__device__ __forceinline__ u64 PK(float x, float y) {
    u64 r;
    asm("mov.b64 %0, {%1,%2};" : "=l"(r) : "f"(x), "f"(y));
    return r;
}
__device__ __forceinline__ float2 UPK(u64 v) {
    float2 f;
    asm("mov.b64 {%0,%1}, %2;" : "=f"(f.x), "=f"(f.y) : "l"(v));
    return f;
}
__device__ __forceinline__ u64 FFMA2(u64 a, u64 b, u64 c) {
    u64 d;
    asm("fma.rn.f32x2 %0, %1, %2, %3;" : "=l"(d) : "l"(a), "l"(b), "l"(c));
    return d;
}
__device__ __forceinline__ float HSUM(u64 v) {
    float2 f = UPK(v);
    return f.x + f.y;
}
__device__ __forceinline__ float fast_tanh(float x) {
    float e = __expf(2.0f * x);
    return 1.0f - __fdividef(2.0f, e + 1.0f);
}
__device__ __forceinline__ float fast_sig(float x) {
    return 1.0f / (1.0f + __expf(-x));
}

// ---------------- scratch ----------------
__device__ float g_sm[NC * NF];
__device__ float g_A[NB * NC * NC];
__device__ u64 g_abits[NB * NC];             // adjacency bitmask per row
__device__ float g_Wh[NB * NT * NC * NGO];   // [bt][c][j]
__device__ float g_gx[2 * NB * NT * 4 * NH];
__device__ float g_hl[NB * NT * 2 * NH];
__device__ float g_sc[NB * NT];

// ---------------- kernel 0: row softmax of spectral_w ----------------
__global__ void k_sm(const float* __restrict__ sw) {
    int c = blockIdx.x, f = threadIdx.x;
    float v = sw[c * NF + f];
    __shared__ float rm[4], rs[4];
    int lane = f & 31, w = f >> 5;
    float m = v;
#pragma unroll
    for (int o = 16; o; o >>= 1) m = fmaxf(m, __shfl_xor_sync(0xffffffffu, m, o));
    if (lane == 0) rm[w] = m;
    __syncthreads();
    m = fmaxf(fmaxf(rm[0], rm[1]), fmaxf(rm[2], rm[3]));
    float e = __expf(v - m);
    float s = e;
#pragma unroll
    for (int o = 16; o; o >>= 1) s += __shfl_xor_sync(0xffffffffu, s, o);
    if (lane == 0) rs[w] = s;
    __syncthreads();
    s = rs[0] + rs[1] + rs[2] + rs[3];
    g_sm[c * NF + f] = e / s;
}

__global__ void k_zeroA(int half) {
    int i = half * (NB * NC * NC / 2) + blockIdx.x * blockDim.x + threadIdx.x;
    g_A[i] = 0.0f;
}

// ---------------- kernel GW: Gram 8x4 + Wh 8x2 per thread, 128 threads ----------------
extern __shared__ u64 shG[];
__global__ void __launch_bounds__(128, 3) kGW(const float* __restrict__ x,
                                              const float* __restrict__ gatW) {
    u64* xA  = shG;                      // [64][XP]
    u64* xB  = shG + 64 * XP;            // [64][XP]
    u64* swP = shG + 2 * 64 * XP;        // [64 f2][XP slots j]
    float* invn = (float*)(shG + 3 * 64 * XP);           // [64]
    float* accS = (float*)(shG + 3 * 64 * XP + 32);      // [32][128] per-thread acc

    const int tid = threadIdx.x;
    const int ty = tid >> 4;        // 0..7
    const int tx = tid & 15;        // 0..15

    const int bid = blockIdx.x;
    const int sIt = (bid * (NB * NT)) / GGRID;
    const int eIt = ((bid + 1) * (NB * NT)) / GGRID;

    for (int i = tid; i < 64 * NGO; i += 128) {
        int f2 = i >> 5, j = i & 31;
        swP[f2 * XP + j] = PK(gatW[(2 * f2) * NGO + j], gatW[(2 * f2 + 1) * NGO + j]);
    }
#pragma unroll
    for (int i = 0; i < 32; i++) accS[i * 128 + tid] = 0.0f;

    int cur_b = sIt >> 8;
    for (int bt = sIt; bt < eIt; bt++) {
        const int b = bt >> 8;
        if (b != cur_b) {
            float* Ab = g_A + cur_b * NC * NC;
#pragma unroll
            for (int r = 0; r < 8; r++)
#pragma unroll
                for (int c = 0; c < 4; c++) {
                    atomicAdd(&Ab[(ty * 8 + r) * NC + tx * 4 + c],
                              accS[(r * 4 + c) * 128 + tid]);
                    accS[(r * 4 + c) * 128 + tid] = 0.0f;
                }
            cur_b = b;
        }
        {
            const float2* x2 = (const float2*)(x + (size_t)bt * NC * NF);
            const float2* s2 = (const float2*)g_sm;
            for (int i = tid; i < NC * NF / 2; i += 128) {
                int c = i >> 6;
                int f2 = i & 63;
                float2 v = x2[i];
                float2 s = s2[i];
                u64* dst = (c & 2) ? xB : xA;
                dst[f2 * XP + (c >> 2) * 2 + (c & 1)] = PK(v.x * s.x, v.y * s.y);
            }
        }
        __syncthreads();   // B1
        if (tid < 64) {
            const u64* src = (tid & 2) ? xB : xA;
            const int off = (tid >> 2) * 2 + (tid & 1);
            u64 n2 = 0ull;
#pragma unroll 8
            for (int f2 = 0; f2 < 64; f2++) {
                u64 v = src[f2 * XP + off];
                n2 = FFMA2(v, v, n2);
            }
            invn[tid] = 1.0f / (sqrtf(HSUM(n2)) + 1e-8f);
        }
        u64 P[32], PW[16];
#pragma unroll
        for (int i = 0; i < 32; i++) P[i] = 0ull;
#pragma unroll
        for (int i = 0; i < 16; i++) PW[i] = 0ull;
        for (int f2 = 0; f2 < 64; f2++) {
            const int base = f2 * XP;
            ulonglong2 aA01 = *(const ulonglong2*)&xA[base + ty * 4];
            ulonglong2 aB01 = *(const ulonglong2*)&xB[base + ty * 4];
            ulonglong2 aA23 = *(const ulonglong2*)&xA[base + ty * 4 + 2];
            ulonglong2 aB23 = *(const ulonglong2*)&xB[base + ty * 4 + 2];
            ulonglong2 bA = *(const ulonglong2*)&xA[base + tx * 2];
            ulonglong2 bB = *(const ulonglong2*)&xB[base + tx * 2];
            ulonglong2 ww = *(const ulonglong2*)&swP[base + tx * 2];
            u64 ar[8];
            ar[0] = aA01.x; ar[1] = aA01.y; ar[2] = aB01.x; ar[3] = aB01.y;
            ar[4] = aA23.x; ar[5] = aA23.y; ar[6] = aB23.x; ar[7] = aB23.y;
            u64 bc0 = bA.x, bc1 = bA.y, bc2 = bB.x, bc3 = bB.y;
#pragma unroll
            for (int r = 0; r < 8; r++) {
                P[r * 4 + 0] = FFMA2(ar[r], bc0, P[r * 4 + 0]);
                P[r * 4 + 1] = FFMA2(ar[r], bc1, P[r * 4 + 1]);
                P[r * 4 + 2] = FFMA2(ar[r], bc2, P[r * 4 + 2]);
                P[r * 4 + 3] = FFMA2(ar[r], bc3, P[r * 4 + 3]);
                PW[r * 2 + 0] = FFMA2(ar[r], ww.x, PW[r * 2 + 0]);
                PW[r * 2 + 1] = FFMA2(ar[r], ww.y, PW[r * 2 + 1]);
            }
        }
        __syncthreads();   // B2
        {
            float* whp = g_Wh + (size_t)bt * NC * NGO + (ty * 8) * NGO + tx * 2;
#pragma unroll
            for (int r = 0; r < 8; r++)
                *(float2*)(whp + r * NGO) =
                    make_float2(HSUM(PW[r * 2]), HSUM(PW[r * 2 + 1]));
        }
        {
            float ir[8], ic[4];
#pragma unroll
            for (int i = 0; i < 8; i++) ir[i] = invn[ty * 8 + i];
#pragma unroll
            for (int i = 0; i < 4; i++) ic[i] = invn[tx * 4 + i];
#pragma unroll
            for (int r = 0; r < 8; r++)
#pragma unroll
                for (int c = 0; c < 4; c++)
                    accS[(r * 4 + c) * 128 + tid] += HSUM(P[r * 4 + c]) * ir[r] * ic[c];
        }
    }
    {
        float* Ab = g_A + cur_b * NC * NC;
#pragma unroll
        for (int r = 0; r < 8; r++)
#pragma unroll
            for (int c = 0; c < 4; c++)
                atomicAdd(&Ab[(ty * 8 + r) * NC + tx * 4 + c],
                          accS[(r * 4 + c) * 128 + tid]);
    }
}

// ---------------- kernel 2: top-4 + symmetrize + adjacency BITMASK ----------------
__global__ void __launch_bounds__(256) k2(void) {
    __shared__ u64 um[NC];
    const int b = blockIdx.x, tid = threadIdx.x;
    const int w = tid >> 5, lane = tid & 31;
    for (int rr = 0; rr < 8; rr++) {
        const int row = w * 8 + rr;
        const float* Ar = g_A + ((size_t)b * NC + row) * NC;
        float v0 = Ar[lane], v1 = Ar[lane + 32];
        u64 mask = 0ull;
#pragma unroll
        for (int r = 0; r < 4; r++) {
            float best; int bi;
            if (v1 > v0) { best = v1; bi = lane + 32; } else { best = v0; bi = lane; }
#pragma unroll
            for (int o = 16; o; o >>= 1) {
                float ov = __shfl_xor_sync(0xffffffffu, best, o);
                int oi = __shfl_xor_sync(0xffffffffu, bi, o);
                if (ov > best || (ov == best && oi < bi)) { best = ov; bi = oi; }
            }
            mask |= 1ull << bi;
            if (bi == lane) v0 = -3.4e38f;
            if (bi == lane + 32) v1 = -3.4e38f;
        }
        if (lane == 0) um[row] = mask & ~(1ull << row);
    }
    __syncthreads();
    if (tid < NC) {
        const int c = tid;
        const float* Ar = g_A + ((size_t)b * NC + c) * NC;
        const u64 uc = um[c];
        u64 bits = 0ull;
        for (int d = 0; d < NC; d++) {
            bool tk = (((uc >> d) | (um[d] >> c)) & 1ull) != 0;
            if (tk && Ar[d] > 0.0f) bits |= 1ull << d;
        }
        bits |= 1ull << c;   // diagonal
        g_abits[b * NC + c] = bits;
    }
}

// ---------------- kernel 3: s1/s2 + SPARSE GAT + pooling + LSTM input gates ----------------
__global__ void __launch_bounds__(256) k3(const float* __restrict__ gata,
                                          const float* __restrict__ pool_w,
                                          const float* __restrict__ pool_b,
                                          const float* __restrict__ Wi_f,
                                          const float* __restrict__ b_f,
                                          const float* __restrict__ Wi_r,
                                          const float* __restrict__ b_r) {
    __shared__ float sWh[NC * 36];   // [c][j], stride 36
    __shared__ float sgat[NC * 33];
    __shared__ float ss1[NC], ss2[NC], pnum[NC];
    __shared__ float pw[NGO], sga[2 * NGO];
    __shared__ float hps[NH];
    __shared__ u64 sbits[NC];

    const int bt = blockIdx.x;
    const int b = bt >> 8;
    const int tid = threadIdx.x;

    const float* whg = g_Wh + (size_t)bt * NC * NGO;
    for (int i = tid; i < NC * NGO; i += 256) {
        int c = i >> 5, j = i & 31;
        sWh[c * 36 + j] = whg[i];
    }
    if (tid < NC) sbits[tid] = g_abits[b * NC + tid];
    if (tid < NGO) pw[tid] = pool_w[tid];
    if (tid < 2 * NGO) sga[tid] = gata[tid];
    __syncthreads();

    if (tid < NC) {
        float a1 = 0.0f, a2 = 0.0f;
        const float* wr = &sWh[tid * 36];
#pragma unroll 8
        for (int j = 0; j < NGO; j++) {
            float w = wr[j];
            a1 += w * sga[j];
            a2 += w * sga[NGO + j];
        }
        ss1[tid] = a1;
        ss2[tid] = a2;
    }
    __syncthreads();

    const int c = tid >> 2, q = tid & 3, j0 = q * 8;
    const float s1c = ss1[c];
    const u64 bits = sbits[c];
    float m = -3.4e38f;
    {
        u64 t = bits;
        while (t) {
            int d = __ffsll((long long)t) - 1;
            t &= t - 1;
            float e = s1c + ss2[d];
            e = (e >= 0.0f) ? e : 0.2f * e;
            m = fmaxf(m, e);
        }
    }
    float acc[8];
#pragma unroll
    for (int i = 0; i < 8; i++) acc[i] = 0.0f;
    float sum = 0.0f;
    {
        u64 t = bits;
        while (t) {
            int d = __ffsll((long long)t) - 1;
            t &= t - 1;
            float e = s1c + ss2[d];
            e = (e >= 0.0f) ? e : 0.2f * e;
            float p = __expf(e - m);
            sum += p;
            float4 w0 = *(const float4*)&sWh[d * 36 + j0];
            float4 w1 = *(const float4*)&sWh[d * 36 + j0 + 4];
            acc[0] += p * w0.x; acc[1] += p * w0.y; acc[2] += p * w0.z; acc[3] += p * w0.w;
            acc[4] += p * w1.x; acc[5] += p * w1.y; acc[6] += p * w1.z; acc[7] += p * w1.w;
        }
    }
    const float inv = 1.0f / sum;
#pragma unroll
    for (int jj = 0; jj < 8; jj++) {
        float g = acc[jj] * inv;
        sgat[c * 33 + j0 + jj] = (g > 0.0f) ? g : 0.0f;
    }
    __syncthreads();

    // pooling
    if (tid < NC) {
        float p = pool_b[0];
#pragma unroll
        for (int o = 0; o < NGO; o++) p += sgat[tid * 33 + o] * pw[o];
        pnum[tid] = p;
    }
    __syncthreads();
    if (tid < 32) {
        float a0 = pnum[tid], a1 = pnum[tid + 32];
        float mx = fmaxf(a0, a1);
#pragma unroll
        for (int o = 16; o; o >>= 1) mx = fmaxf(mx, __shfl_xor_sync(0xffffffffu, mx, o));
        float e0 = __expf(a0 - mx), e1 = __expf(a1 - mx);
        float sm = e0 + e1;
#pragma unroll
        for (int o = 16; o; o >>= 1) sm += __shfl_xor_sync(0xffffffffu, sm, o);
        pnum[tid] = e0 / sm;
        pnum[tid + 32] = e1 / sm;
    }
    __syncthreads();
    if (tid < NGO) {
        float hv = 0.0f;
#pragma unroll 4
        for (int c2 = 0; c2 < NC; c2++) hv += sgat[c2 * 33 + tid] * pnum[c2];
        hps[tid] = hv;
    }
    __syncthreads();

    // fused LSTM input gates: gx[dir][j] = b[j] + hp @ Wi_dir[:,j]
    {
        const int dir = tid >> 7, j = tid & 127;
        const float* Wi = dir ? Wi_r : Wi_f;
        const float* bias = dir ? b_r : b_f;
        float a = bias[j];
#pragma unroll 8
        for (int k = 0; k < NH; k++) a += hps[k] * __ldg(&Wi[k * 128 + j]);
        g_gx[((size_t)dir * 4096 + bt) * 128 + j] = a;
    }
}

// ---------------- kernel 4b: LSTM recurrence (1 warp, k-packed gates) ----------------
__global__ void __launch_bounds__(32) k4b(const float* __restrict__ Wh_f,
                                          const float* __restrict__ Wh_r) {
    const int dir = blockIdx.x >> 4;
    const int b = blockIdx.x & 15;
    const float* Wh = dir ? Wh_r : Wh_f;
    const int j = threadIdx.x;
    u64 wi[16], wf[16], wg[16], wo[16];
#pragma unroll
    for (int kp = 0; kp < 16; kp++) {
        const float* ra = Wh + (2 * kp) * 128;
        const float* rb = Wh + (2 * kp + 1) * 128;
        wi[kp] = PK(ra[j],      rb[j]);
        wf[kp] = PK(ra[j + 32], rb[j + 32]);
        wg[kp] = PK(ra[j + 64], rb[j + 64]);
        wo[kp] = PK(ra[j + 96], rb[j + 96]);
    }
    const float* gx = g_gx + ((size_t)dir * 4096 + b * NT) * 128;
    float h = 0.0f, cst = 0.0f;
    int t = dir ? (NT - 1) : 0;
    const int st = dir ? -1 : 1;
    const float* g0p = gx + t * 128;
    float c0 = g0p[j], c1 = g0p[j + 32], c2 = g0p[j + 64], c3 = g0p[j + 96];
    for (int s = 0; s < NT; s++) {
        const int tn = t + st;
        float n0 = 0.0f, n1 = 0.0f, n2 = 0.0f, n3 = 0.0f;
        if (s < NT - 1) {
            const float* gn = gx + tn * 128;
            n0 = gn[j]; n1 = gn[j + 32]; n2 = gn[j + 64]; n3 = gn[j + 96];
        }
        u64 ai = 0ull, af = 0ull, ag = 0ull, ao = 0ull;
#pragma unroll
        for (int kp = 0; kp < 16; kp++) {
            float h0 = __shfl_sync(0xffffffffu, h, 2 * kp);
            float h1 = __shfl_sync(0xffffffffu, h, 2 * kp + 1);
            u64 hp = PK(h0, h1);
            ai = FFMA2(hp, wi[kp], ai);
            af = FFMA2(hp, wf[kp], af);
            ag = FFMA2(hp, wg[kp], ag);
            ao = FFMA2(hp, wo[kp], ao);
        }
        float gi = c0 + HSUM(ai), gf = c1 + HSUM(af);
        float gg = c2 + HSUM(ag), go = c3 + HSUM(ao);
        float ig = fast_sig(gi), fg = fast_sig(gf), og = fast_sig(go);
        cst = fg * cst + ig * fast_tanh(gg);
        h = og * fast_tanh(cst);
        g_hl[(size_t)(b * NT + t) * 64 + dir * NH + j] = h;
        c0 = n0; c1 = n1; c2 = n2; c3 = n3;
        t = tn;
    }
}

// ---------------- kernel 5a: temporal attention scores (16x parallel) ----------------
__global__ void __launch_bounds__(256) k5a(const float* __restrict__ taW,
                                           const float* __restrict__ tab,
                                           const float* __restrict__ tav) {
    __shared__ __align__(16) float sWt[64 * 68];   // [jj][k] transposed
    __shared__ __align__(16) float sh[16 * 68];    // h rows for 16 timesteps
    __shared__ float stb[64], stv[64];
    const int tid = threadIdx.x;
    const int b = blockIdx.x >> 4;
    const int t0 = (blockIdx.x & 15) * 16;
    for (int i = tid; i < 4096; i += 256) {
        int k = i >> 6, jj = i & 63;
        sWt[jj * 68 + k] = taW[i];
    }
    for (int i = tid; i < 16 * 64; i += 256) {
        int tl = i >> 6, k = i & 63;
        sh[tl * 68 + k] = g_hl[(size_t)(b * NT + t0 + tl) * 64 + k];
    }
    if (tid < 64) { stb[tid] = tab[tid]; stv[tid] = tav[tid]; }
    __syncthreads();
    const int tl = tid >> 4, jg = tid & 15;
    const float* hrow = &sh[tl * 68];
    float sc = 0.0f;
#pragma unroll
    for (int u = 0; u < 4; u++) {
        const int jj = jg * 4 + u;
        const float* wr = &sWt[jj * 68];
        u64 a0 = PK(stb[jj], 0.0f), a1 = 0ull;
#pragma unroll
        for (int k = 0; k < 64; k += 4) {
            ulonglong2 hv = *(const ulonglong2*)&hrow[k];
            ulonglong2 wv = *(const ulonglong2*)&wr[k];
            a0 = FFMA2(hv.x, wv.x, a0);
            a1 = FFMA2(hv.y, wv.y, a1);
        }
        sc += fast_tanh(HSUM(a0) + HSUM(a1)) * stv[jj];
    }
#pragma unroll
    for (int o = 8; o; o >>= 1) sc += __shfl_xor_sync(0xffffffffu, sc, o);
    if (jg == 0) g_sc[b * NT + t0 + tl] = sc * (1.0f / 1.5f);
}

// ---------------- kernel 5b: softmax + ctx + LN + MLP head ----------------
__global__ void k5b(const float* __restrict__ lng, const float* __restrict__ lnb,
                    const float* __restrict__ f1w, const float* __restrict__ f1b,
                    const float* __restrict__ f2w, const float* __restrict__ f2b,
                    float* __restrict__ out) {
    const int b = blockIdx.x, t = threadIdx.x;
    __shared__ float sal[NT];
    __shared__ float wr[8];
    __shared__ float part[4][64];
    __shared__ float ctxs[64];
    __shared__ float y1s[32];
    __shared__ float stats[2];
    float sc = g_sc[b * NT + t];
    const int lane = t & 31, w = t >> 5;
    float m = sc;
#pragma unroll
    for (int o = 16; o; o >>= 1) m = fmaxf(m, __shfl_xor_sync(0xffffffffu, m, o));
    if (lane == 0) wr[w] = m;
    __syncthreads();
    m = wr[0];
#pragma unroll
    for (int i = 1; i < 8; i++) m = fmaxf(m, wr[i]);
    float e = __expf(sc - m);
    float s = e;
#pragma unroll
    for (int o = 16; o; o >>= 1) s += __shfl_xor_sync(0xffffffffu, s, o);
    __syncthreads();
    if (lane == 0) wr[w] = s;
    __syncthreads();
    s = 0.0f;
#pragma unroll
    for (int i = 0; i < 8; i++) s += wr[i];
    sal[t] = e / s;
    __syncthreads();
    {
        const int k = t & 63, q4 = t >> 6;
        float cx = 0.0f;
        const float* hb = g_hl + (size_t)b * NT * 64;
        for (int tt = q4 * 64; tt < q4 * 64 + 64; tt++)
            cx += hb[(size_t)tt * 64 + k] * sal[tt];
        part[q4][k] = cx;
    }
    __syncthreads();
    if (t < 64) ctxs[t] = part[0][t] + part[1][t] + part[2][t] + part[3][t];
    __syncthreads();
    if (t == 0) {
        float mean = 0.0f;
        for (int k = 0; k < 64; k++) mean += ctxs[k];
        mean *= (1.0f / 64.0f);
        float var = 0.0f;
        for (int k = 0; k < 64; k++) { float d2 = ctxs[k] - mean; var += d2 * d2; }
        var *= (1.0f / 64.0f);
        stats[0] = mean;
        stats[1] = rsqrtf(var + 1e-5f);
    }
    __syncthreads();
    if (t < 64) ctxs[t] = (ctxs[t] - stats[0]) * stats[1] * lng[t] + lnb[t];
    __syncthreads();
    if (t < 32) {
        float a = f1b[t];
#pragma unroll
        for (int k = 0; k < 64; k++) a += ctxs[k] * f1w[k * 32 + t];
        y1s[t] = (a > 0.0f) ? a : 0.0f;
    }
    __syncthreads();
    if (t < 3) {
        float o = f2b[t];
#pragma unroll
        for (int m2 = 0; m2 < 32; m2++) o += y1s[m2] * f2w[m2 * 3 + t];
        out[b * 3 + t] = o;
    }
}

// ---------------- launcher ----------------
extern "C" void kernel_launch(void* const* d_in, const int* in_sizes, int n_in,
                              void* d_out, int out_size) {
    const float* x       = (const float*)d_in[0];
    const float* spec_w  = (const float*)d_in[1];
    const float* gat_W   = (const float*)d_in[2];
    const float* gat_a   = (const float*)d_in[3];
    const float* pool_w  = (const float*)d_in[4];
    const float* pool_b  = (const float*)d_in[5];
    const float* Wi_f    = (const float*)d_in[6];
    const float* Wh_f    = (const float*)d_in[7];
    const float* b_f     = (const float*)d_in[8];
    const float* Wi_r    = (const float*)d_in[9];
    const float* Wh_r    = (const float*)d_in[10];
    const float* b_r     = (const float*)d_in[11];
    const float* taW     = (const float*)d_in[12];
    const float* tab     = (const float*)d_in[13];
    const float* tav     = (const float*)d_in[14];
    const float* lng     = (const float*)d_in[15];
    const float* lnb     = (const float*)d_in[16];
    const float* f1w     = (const float*)d_in[17];
    const float* f1b     = (const float*)d_in[18];
    const float* f2w     = (const float*)d_in[19];
    const float* f2b     = (const float*)d_in[20];

    // smem: xA+xB+swP (3*64*XP u64) + invn pad (32 u64) + accS (32*128 f)
    const int kG_smem = (3 * 64 * XP + 32) * 8 + 32 * 128 * 4;   // 68864 B
    cudaFuncSetAttribute(kGW, cudaFuncAttributeMaxDynamicSharedMemorySize, kG_smem);

    k_sm<<<64, 128>>>(spec_w);                        // launch 1
    k_zeroA<<<NB * NC * NC / 512, 256>>>(0);          // launch 2
    k_zeroA<<<NB * NC * NC / 512, 256>>>(1);          // launch 3
    kGW<<<GGRID, 128, kG_smem>>>(x, gat_W);           // launch 4 <- profiled
    k2<<<NB, 256>>>();                                // launch 5
    k3<<<NB * NT, 256>>>(gat_a, pool_w, pool_b, Wi_f, b_f, Wi_r, b_r);
    k4b<<<32, 32>>>(Wh_f, Wh_r);
    k5a<<<NB * 16, 256>>>(taW, tab, tav);
    k5b<<<NB, 256>>>(lng, lnb, f1w, f1b, f2w, f2b, (float*)d_out);
}